// round 1
// baseline (speedup 1.0000x reference)
#include <cuda_runtime.h>

// ---------------------------------------------------------------------------
// GraphSAGE (LSTM aggregation), 2 layers. N=50000, DEG=8, F_IN=64, HID=LH=128.
// Per layer: 8 fused LSTM-step GEMMs  gates = [x[src_t] | h] @ Bc + b   (K=F+128)
// then      out = LayerNorm(ReLU([x | h_final] @ linW^T + b)) (* relu between layers)
// ---------------------------------------------------------------------------

namespace cfg {
constexpr int N    = 50000;
constexpr int DEG  = 8;
constexpr int E    = N * DEG;
constexpr int F1   = 64;
constexpr int HID  = 128;
constexpr int LH   = 128;
constexpr int G4   = 4 * LH;            // 512 gate columns
constexpr int TM   = 64;                // nodes per block
constexpr int TC   = 128;               // gate columns per block
constexpr int NTHR = 256;
constexpr int AST  = TM + 4;            // A_T row stride (68, 16B-aligned, odd/32 banks)
constexpr int MB   = (N + TM - 1) / TM; // 782
constexpr float EPS = 1e-5f;
}
using namespace cfg;

// ------------------------- device scratch (no allocs) ----------------------
__device__ float g_Bc1[(F1 + LH) * G4];   // interleaved [K][512], col = u*4+gate
__device__ float g_Bc2[(HID + LH) * G4];
__device__ float g_bc1[G4];
__device__ float g_bc2[G4];
__device__ float g_L1T[(F1 + LH) * HID];  // lin W transposed [K][HID]
__device__ float g_L2T[(HID + LH) * HID];
__device__ float g_hA[N * LH];            // h double buffer
__device__ float g_hB[N * LH];
__device__ float g_cS[N * LH];            // cell state
__device__ float g_h1[N * HID];           // layer-1 output (post relu)
__device__ int   g_src[E];                // normalized int32 source indices

// ------------------------- helpers -----------------------------------------
__device__ __forceinline__ float sigf(float x) {
    return __fdividef(1.0f, 1.0f + __expf(-x));
}
__device__ __forceinline__ float tanhfast(float x) {
    return __fdividef(2.0f, 1.0f + __expf(-2.0f * x)) - 1.0f;
}

// Normalize edge_index src row to int32, robust to int64-vs-int32 dtype.
// If data is int64 (little-endian), every odd int32 word of the first 64 is 0.
__global__ void cvt_src_kernel(const int* __restrict__ raw) {
    bool w64 = true;
#pragma unroll
    for (int i = 0; i < 32; i++) w64 &= (raw[2 * i + 1] == 0);
    for (int idx = blockIdx.x * blockDim.x + threadIdx.x; idx < E;
         idx += gridDim.x * blockDim.x)
        g_src[idx] = w64 ? raw[2 * idx] : raw[idx];
}

// Build interleaved/transposed weights once per call (cheap, deterministic).
__global__ void prep_kernel(const float* __restrict__ W1ih, const float* __restrict__ W1hh,
                            const float* __restrict__ b1,   const float* __restrict__ l1W,
                            const float* __restrict__ W2ih, const float* __restrict__ W2hh,
                            const float* __restrict__ b2,   const float* __restrict__ l2W) {
    const int stride = gridDim.x * blockDim.x;
    const int t0 = blockIdx.x * blockDim.x + threadIdx.x;
    constexpr int K1 = F1 + LH, K2 = HID + LH;
    for (int idx = t0; idx < K1 * G4; idx += stride) {
        int k = idx / G4, cc = idx % G4, u = cc >> 2, g = cc & 3, row = g * LH + u;
        g_Bc1[idx] = (k < F1) ? W1ih[row * F1 + k] : W1hh[row * LH + (k - F1)];
    }
    for (int idx = t0; idx < K2 * G4; idx += stride) {
        int k = idx / G4, cc = idx % G4, u = cc >> 2, g = cc & 3, row = g * LH + u;
        g_Bc2[idx] = (k < HID) ? W2ih[row * HID + k] : W2hh[row * LH + (k - HID)];
    }
    for (int idx = t0; idx < G4; idx += stride) {
        int u = idx >> 2, g = idx & 3;
        g_bc1[idx] = b1[g * LH + u];
        g_bc2[idx] = b2[g * LH + u];
    }
    for (int idx = t0; idx < K1 * HID; idx += stride) {
        int k = idx / HID, cc = idx % HID;
        g_L1T[idx] = l1W[cc * K1 + k];
    }
    for (int idx = t0; idx < K2 * HID; idx += stride) {
        int k = idx / HID, cc = idx % HID;
        g_L2T[idx] = l2W[cc * K2 + k];
    }
}

// ------------------------- LSTM step ----------------------------------------
// gates[TM x TC] = [x[src_t] | h_in][TM x K] @ Bc_slice[K x TC] (+ bias),
// then elementwise c/h update for the 32 hidden units this block owns.
template <int F, bool FIRST>
__global__ void __launch_bounds__(NTHR, 1)
lstm_step_kernel(const float* __restrict__ xin, int t,
                 const float* __restrict__ Bc, const float* __restrict__ bc,
                 const float* __restrict__ hin, float* __restrict__ hout,
                 float* __restrict__ cst) {
    constexpr int K = FIRST ? F : (F + LH);
    extern __shared__ float smem[];
    float* sA = smem;            // A transposed: [K][AST]
    float* sB = smem + K * AST;  // [K][TC]
    __shared__ int sSrc[TM];

    const int tid = threadIdx.x;
    const int m0  = blockIdx.x * TM;
    const int c0  = blockIdx.y * TC;

    if (tid < TM) {
        int n = m0 + tid;
        sSrc[tid] = (n < N) ? g_src[n * DEG + t] : 0;
    }
    __syncthreads();

    // A_T: gathered x rows
    for (int idx = tid; idx < TM * F; idx += NTHR) {
        int m = idx / F, k = idx % F;
        float v = (m0 + m < N) ? xin[(long)sSrc[m] * F + k] : 0.0f;
        sA[k * AST + m] = v;
    }
    if (!FIRST) {
        for (int idx = tid; idx < TM * LH; idx += NTHR) {
            int m = idx / LH, k = idx % LH;
            float v = (m0 + m < N) ? hin[(m0 + m) * LH + k] : 0.0f;
            sA[(F + k) * AST + m] = v;
        }
    }
    // B slice
    for (int idx = tid; idx < K * TC; idx += NTHR) {
        int k = idx / TC, cc = idx % TC;
        sB[idx] = Bc[k * G4 + c0 + cc];
    }
    __syncthreads();

    const int nIdx = tid & 15;  // 16 col-groups x 8 cols
    const int mIdx = tid >> 4;  // 16 node-groups x 4 nodes
    const float* pa = sA + mIdx * 4;
    const float* pb = sB + nIdx * 8;

    float acc[4][8];
#pragma unroll
    for (int i = 0; i < 4; i++)
#pragma unroll
        for (int j = 0; j < 8; j++) acc[i][j] = bc[c0 + nIdx * 8 + j];

#pragma unroll 4
    for (int k = 0; k < K; k++) {
        float4 av  = *reinterpret_cast<const float4*>(pa + k * AST);
        float4 bv0 = *reinterpret_cast<const float4*>(pb + k * TC);
        float4 bv1 = *reinterpret_cast<const float4*>(pb + k * TC + 4);
        float a[4] = {av.x, av.y, av.z, av.w};
        float b[8] = {bv0.x, bv0.y, bv0.z, bv0.w, bv1.x, bv1.y, bv1.z, bv1.w};
#pragma unroll
        for (int i = 0; i < 4; i++)
#pragma unroll
            for (int j = 0; j < 8; j++) acc[i][j] = fmaf(a[i], b[j], acc[i][j]);
    }

    // epilogue: cols are interleaved (unit*4 + gate): j 0..3 -> unit u0, 4..7 -> u0+1
    const int u0 = (c0 >> 2) + nIdx * 2;
#pragma unroll
    for (int i = 0; i < 4; i++) {
        int n = m0 + mIdx * 4 + i;
        if (n < N) {
#pragma unroll
            for (int uu = 0; uu < 2; uu++) {
                float gi = sigf(acc[i][uu * 4 + 0]);
                float gf = sigf(acc[i][uu * 4 + 1]);
                float gg = tanhfast(acc[i][uu * 4 + 2]);
                float go = sigf(acc[i][uu * 4 + 3]);
                int u = u0 + uu;
                float cold = FIRST ? 0.0f : cst[n * LH + u];
                float cn = gf * cold + gi * gg;
                cst[n * LH + u]  = cn;
                hout[n * LH + u] = go * tanhfast(cn);
            }
        }
    }
}

// ------------------------- linear + ReLU + LayerNorm ------------------------
template <int F, bool RELU_OUT>
__global__ void __launch_bounds__(NTHR, 1)
out_kernel(const float* __restrict__ xin, const float* __restrict__ hfin,
           const float* __restrict__ LT, const float* __restrict__ lb,
           const float* __restrict__ gma, const float* __restrict__ bta,
           float* __restrict__ out) {
    constexpr int K = F + LH;
    constexpr int VST = HID + 4;
    extern __shared__ float smem[];
    float* sA = smem;            // [K][AST]
    float* sB = smem + K * AST;  // [K][HID]; reused as sV [TM][VST] after compute
    float* sV = sB;
    __shared__ float sMu[TM], sR[TM];

    const int tid = threadIdx.x;
    const int m0  = blockIdx.x * TM;

    for (int idx = tid; idx < TM * F; idx += NTHR) {
        int m = idx / F, k = idx % F;
        sA[k * AST + m] = (m0 + m < N) ? xin[(m0 + m) * F + k] : 0.0f;
    }
    for (int idx = tid; idx < TM * LH; idx += NTHR) {
        int m = idx / LH, k = idx % LH;
        sA[(F + k) * AST + m] = (m0 + m < N) ? hfin[(m0 + m) * LH + k] : 0.0f;
    }
    for (int idx = tid; idx < K * HID; idx += NTHR) sB[idx] = LT[idx];
    __syncthreads();

    const int nIdx = tid & 15;
    const int mIdx = tid >> 4;
    const float* pa = sA + mIdx * 4;
    const float* pb = sB + nIdx * 8;

    float acc[4][8];
#pragma unroll
    for (int i = 0; i < 4; i++)
#pragma unroll
        for (int j = 0; j < 8; j++) acc[i][j] = lb[nIdx * 8 + j];

#pragma unroll 4
    for (int k = 0; k < K; k++) {
        float4 av  = *reinterpret_cast<const float4*>(pa + k * AST);
        float4 bv0 = *reinterpret_cast<const float4*>(pb + k * HID);
        float4 bv1 = *reinterpret_cast<const float4*>(pb + k * HID + 4);
        float a[4] = {av.x, av.y, av.z, av.w};
        float b[8] = {bv0.x, bv0.y, bv0.z, bv0.w, bv1.x, bv1.y, bv1.z, bv1.w};
#pragma unroll
        for (int i = 0; i < 4; i++)
#pragma unroll
            for (int j = 0; j < 8; j++) acc[i][j] = fmaf(a[i], b[j], acc[i][j]);
    }
    __syncthreads();  // all sB reads done before overlaying sV

#pragma unroll
    for (int i = 0; i < 4; i++)
#pragma unroll
        for (int j = 0; j < 8; j++)
            sV[(mIdx * 4 + i) * VST + nIdx * 8 + j] = fmaxf(acc[i][j], 0.0f);
    __syncthreads();

    if (tid < TM) {
        float s = 0.0f, s2 = 0.0f;
        for (int cidx = 0; cidx < HID; cidx++) {
            float v = sV[tid * VST + cidx];
            s += v; s2 += v * v;
        }
        float mu  = s * (1.0f / HID);
        float var = s2 * (1.0f / HID) - mu * mu;
        sMu[tid] = mu;
        sR[tid]  = rsqrtf(var + EPS);
    }
    __syncthreads();

    for (int idx = tid; idx < TM * HID; idx += NTHR) {
        int m = idx / HID, cc = idx % HID;
        int n = m0 + m;
        if (n < N) {
            float v = (sV[m * VST + cc] - sMu[m]) * sR[m] * gma[cc] + bta[cc];
            out[n * HID + cc] = RELU_OUT ? fmaxf(v, 0.0f) : v;
        }
    }
}

// ------------------------- launch --------------------------------------------
extern "C" void kernel_launch(void* const* d_in, const int* in_sizes, int n_in,
                              void* d_out, int out_size) {
    const float* x    = (const float*)d_in[0];
    const int*   eraw = (const int*)d_in[1];   // edge_index (int64 or int32)
    const float* W1ih = (const float*)d_in[2];
    const float* W1hh = (const float*)d_in[3];
    const float* b1   = (const float*)d_in[4];
    const float* l1W  = (const float*)d_in[5];
    const float* l1b  = (const float*)d_in[6];
    const float* g1   = (const float*)d_in[7];
    const float* be1  = (const float*)d_in[8];
    const float* W2ih = (const float*)d_in[9];
    const float* W2hh = (const float*)d_in[10];
    const float* b2   = (const float*)d_in[11];
    const float* l2W  = (const float*)d_in[12];
    const float* l2b  = (const float*)d_in[13];
    const float* g2   = (const float*)d_in[14];
    const float* be2  = (const float*)d_in[15];

    float *pBc1, *pBc2, *pbc1, *pbc2, *pL1, *pL2, *phA, *phB, *pc, *ph1;
    cudaGetSymbolAddress((void**)&pBc1, g_Bc1);
    cudaGetSymbolAddress((void**)&pBc2, g_Bc2);
    cudaGetSymbolAddress((void**)&pbc1, g_bc1);
    cudaGetSymbolAddress((void**)&pbc2, g_bc2);
    cudaGetSymbolAddress((void**)&pL1, g_L1T);
    cudaGetSymbolAddress((void**)&pL2, g_L2T);
    cudaGetSymbolAddress((void**)&phA, g_hA);
    cudaGetSymbolAddress((void**)&phB, g_hB);
    cudaGetSymbolAddress((void**)&pc, g_cS);
    cudaGetSymbolAddress((void**)&ph1, g_h1);

    // dynamic smem sizes (bytes)
    const int s1f = (F1 * AST + F1 * TC) * 4;                       //  50,176
    const int s1  = ((F1 + LH) * AST + (F1 + LH) * TC) * 4;         // 150,528
    const int s2f = (HID * AST + HID * TC) * 4;                     // 100,352
    const int s2  = ((HID + LH) * AST + (HID + LH) * TC) * 4;       // 200,704
    const int o1  = ((F1 + LH) * AST + (F1 + LH) * HID) * 4;        // 150,528
    const int o2  = ((HID + LH) * AST + (HID + LH) * HID) * 4;      // 200,704

    cudaFuncSetAttribute((const void*)lstm_step_kernel<F1, true>,
                         cudaFuncAttributeMaxDynamicSharedMemorySize, s1f);
    cudaFuncSetAttribute((const void*)lstm_step_kernel<F1, false>,
                         cudaFuncAttributeMaxDynamicSharedMemorySize, s1);
    cudaFuncSetAttribute((const void*)lstm_step_kernel<HID, true>,
                         cudaFuncAttributeMaxDynamicSharedMemorySize, s2f);
    cudaFuncSetAttribute((const void*)lstm_step_kernel<HID, false>,
                         cudaFuncAttributeMaxDynamicSharedMemorySize, s2);
    cudaFuncSetAttribute((const void*)out_kernel<F1, true>,
                         cudaFuncAttributeMaxDynamicSharedMemorySize, o1);
    cudaFuncSetAttribute((const void*)out_kernel<HID, false>,
                         cudaFuncAttributeMaxDynamicSharedMemorySize, o2);

    cvt_src_kernel<<<(E + 1023) / 1024, 1024>>>(eraw);
    prep_kernel<<<256, 256>>>(W1ih, W1hh, b1, l1W, W2ih, W2hh, b2, l2W);

    const dim3 sgrid(MB, G4 / TC);  // 782 x 4

    // ---------------- layer 1 ----------------
    // step t writes h buffer (t&1); reads the other.
    lstm_step_kernel<F1, true><<<sgrid, NTHR, s1f>>>(x, 0, pBc1, pbc1,
                                                     phB, phA, pc);
    for (int t = 1; t < DEG; t++) {
        float* hw = (t & 1) ? phB : phA;
        float* hr = (t & 1) ? phA : phB;
        lstm_step_kernel<F1, false><<<sgrid, NTHR, s1>>>(x, t, pBc1, pbc1,
                                                         hr, hw, pc);
    }
    // DEG-1 = 7 is odd -> final h in phB
    out_kernel<F1, true><<<MB, NTHR, o1>>>(x, phB, pL1, l1b, g1, be1, ph1);

    // ---------------- layer 2 ----------------
    lstm_step_kernel<HID, true><<<sgrid, NTHR, s2f>>>(ph1, 0, pBc2, pbc2,
                                                      phB, phA, pc);
    for (int t = 1; t < DEG; t++) {
        float* hw = (t & 1) ? phB : phA;
        float* hr = (t & 1) ? phA : phB;
        lstm_step_kernel<HID, false><<<sgrid, NTHR, s2>>>(ph1, t, pBc2, pbc2,
                                                          hr, hw, pc);
    }
    out_kernel<HID, false><<<MB, NTHR, o2>>>(ph1, phB, pL2, l2b, g2, be2,
                                             (float*)d_out);
}

// round 2
// speedup vs baseline: 1.3878x; 1.3878x over previous
#include <cuda_runtime.h>

typedef unsigned long long u64;

// ---------------------------------------------------------------------------
// GraphSAGE (LSTM aggregation), 2 layers. N=50000, DEG=8, F_IN=64, HID=LH=128.
// R2: packed fma.rn.f32x2 inner loop (mov-free via duplicated-A smem layout)
//     + K-tiled smem (KT=64) for 3 CTAs/SM occupancy.
// ---------------------------------------------------------------------------

namespace cfg {
constexpr int N    = 50000;
constexpr int DEG  = 8;
constexpr int E    = N * DEG;
constexpr int F1   = 64;
constexpr int HID  = 128;
constexpr int LH   = 128;
constexpr int G4   = 4 * LH;             // 512 gate columns
constexpr int TM   = 64;                 // nodes per block
constexpr int TC   = 128;                // gate columns per block
constexpr int NTHR = 256;
constexpr int KT   = 64;                 // K tile
constexpr int AST2 = 2 * TM + 4;         // dup-A row stride (132 floats, 16B mult)
constexpr int VST  = HID + 4;            // 132
constexpr int MB   = (N + TM - 1) / TM;  // 782
constexpr float EPS = 1e-5f;
}
using namespace cfg;

// ------------------------- device scratch (no allocs) ----------------------
__device__ float g_Bc1[(F1 + LH) * G4];   // interleaved [K][512], col = u*4+gate
__device__ float g_Bc2[(HID + LH) * G4];
__device__ float g_bc1[G4];
__device__ float g_bc2[G4];
__device__ float g_L1T[(F1 + LH) * HID];  // lin W transposed [K][HID]
__device__ float g_L2T[(HID + LH) * HID];
__device__ float g_hA[N * LH];            // h double buffer
__device__ float g_hB[N * LH];
__device__ float g_cS[N * LH];            // cell state
__device__ float g_h1[N * HID];           // layer-1 output (post relu)
__device__ int   g_src[E];                // normalized int32 source indices

// ------------------------- helpers -----------------------------------------
__device__ __forceinline__ float sigf(float x) {
    return __fdividef(1.0f, 1.0f + __expf(-x));
}
__device__ __forceinline__ float tanhfast(float x) {
    return __fdividef(2.0f, 1.0f + __expf(-2.0f * x)) - 1.0f;
}
__device__ __forceinline__ void fma2(u64& d, u64 a, u64 b) {
    asm("fma.rn.f32x2 %0, %1, %2, %0;" : "+l"(d) : "l"(a), "l"(b));
}

// Normalize edge_index src row to int32, robust to int64-vs-int32 dtype.
__global__ void cvt_src_kernel(const int* __restrict__ raw) {
    bool w64 = true;
#pragma unroll
    for (int i = 0; i < 32; i++) w64 &= (raw[2 * i + 1] == 0);
    for (int idx = blockIdx.x * blockDim.x + threadIdx.x; idx < E;
         idx += gridDim.x * blockDim.x)
        g_src[idx] = w64 ? raw[2 * idx] : raw[idx];
}

// Build interleaved/transposed weights once per call.
__global__ void prep_kernel(const float* __restrict__ W1ih, const float* __restrict__ W1hh,
                            const float* __restrict__ b1,   const float* __restrict__ l1W,
                            const float* __restrict__ W2ih, const float* __restrict__ W2hh,
                            const float* __restrict__ b2,   const float* __restrict__ l2W) {
    const int stride = gridDim.x * blockDim.x;
    const int t0 = blockIdx.x * blockDim.x + threadIdx.x;
    constexpr int K1 = F1 + LH, K2 = HID + LH;
    for (int idx = t0; idx < K1 * G4; idx += stride) {
        int k = idx / G4, cc = idx % G4, u = cc >> 2, g = cc & 3, row = g * LH + u;
        g_Bc1[idx] = (k < F1) ? W1ih[row * F1 + k] : W1hh[row * LH + (k - F1)];
    }
    for (int idx = t0; idx < K2 * G4; idx += stride) {
        int k = idx / G4, cc = idx % G4, u = cc >> 2, g = cc & 3, row = g * LH + u;
        g_Bc2[idx] = (k < HID) ? W2ih[row * HID + k] : W2hh[row * LH + (k - HID)];
    }
    for (int idx = t0; idx < G4; idx += stride) {
        int u = idx >> 2, g = idx & 3;
        g_bc1[idx] = b1[g * LH + u];
        g_bc2[idx] = b2[g * LH + u];
    }
    for (int idx = t0; idx < K1 * HID; idx += stride) {
        int k = idx / HID, cc = idx % HID;
        g_L1T[idx] = l1W[cc * K1 + k];
    }
    for (int idx = t0; idx < K2 * HID; idx += stride) {
        int k = idx / HID, cc = idx % HID;
        g_L2T[idx] = l2W[cc * K2 + k];
    }
}

// Load one K-tile of the A operand (gathered x for k<F, h rows for k>=F) into
// duplicated-layout smem: sA[kk][2m] = sA[kk][2m+1] = a(m, k0+kk).
// Tiles never straddle the x/h boundary (F and KT are both multiples of 64).
template <int F, bool FIRST>
__device__ __forceinline__ void load_A_tile(float* sA, const float* __restrict__ xin,
                                            const float* __restrict__ hin,
                                            const int* sSrc, int m0, int k0, int tid) {
    if (k0 < F) {
        for (int idx = tid; idx < TM * (KT / 4); idx += NTHR) {
            int m = idx >> 4, q = idx & 15;
            float4 v = make_float4(0.f, 0.f, 0.f, 0.f);
            if (m0 + m < N)
                v = *reinterpret_cast<const float4*>(xin + (size_t)sSrc[m] * F + k0 + q * 4);
            float* d = sA + (q * 4) * AST2 + 2 * m;
            *reinterpret_cast<float2*>(d)            = make_float2(v.x, v.x);
            *reinterpret_cast<float2*>(d + AST2)     = make_float2(v.y, v.y);
            *reinterpret_cast<float2*>(d + 2 * AST2) = make_float2(v.z, v.z);
            *reinterpret_cast<float2*>(d + 3 * AST2) = make_float2(v.w, v.w);
        }
    } else if (!FIRST) {
        for (int idx = tid; idx < TM * (KT / 4); idx += NTHR) {
            int m = idx >> 4, q = idx & 15;
            float4 v = make_float4(0.f, 0.f, 0.f, 0.f);
            if (m0 + m < N)
                v = *reinterpret_cast<const float4*>(hin + (size_t)(m0 + m) * LH + (k0 - F) + q * 4);
            float* d = sA + (q * 4) * AST2 + 2 * m;
            *reinterpret_cast<float2*>(d)            = make_float2(v.x, v.x);
            *reinterpret_cast<float2*>(d + AST2)     = make_float2(v.y, v.y);
            *reinterpret_cast<float2*>(d + 2 * AST2) = make_float2(v.z, v.z);
            *reinterpret_cast<float2*>(d + 3 * AST2) = make_float2(v.w, v.w);
        }
    }
}

// ------------------------- LSTM step ----------------------------------------
template <int F, bool FIRST>
__global__ void __launch_bounds__(NTHR, 3)
lstm_step_kernel(const float* __restrict__ xin, int t,
                 const float* __restrict__ Bc, const float* __restrict__ bc,
                 const float* __restrict__ hin, float* __restrict__ hout,
                 float* __restrict__ cst) {
    constexpr int K  = FIRST ? F : (F + LH);
    constexpr int NT = K / KT;
    extern __shared__ float smem[];
    float* sA = smem;              // [KT][AST2] duplicated A
    float* sB = smem + KT * AST2;  // [KT][TC]
    __shared__ int sSrc[TM];

    const int tid = threadIdx.x;
    const int m0  = blockIdx.x * TM;
    const int c0  = blockIdx.y * TC;
    const int nIdx = tid & 15;
    const int mIdx = tid >> 4;

    if (tid < TM) {
        int n = m0 + tid;
        sSrc[tid] = (n < N) ? g_src[n * DEG + t] : 0;
    }

    u64 acc[4][4];
    {
        const ulonglong2* bp = reinterpret_cast<const ulonglong2*>(bc + c0 + nIdx * 8);
        ulonglong2 b0 = bp[0], b1 = bp[1];
        u64 bj[4] = {b0.x, b0.y, b1.x, b1.y};
#pragma unroll
        for (int i = 0; i < 4; i++)
#pragma unroll
            for (int j = 0; j < 4; j++) acc[i][j] = bj[j];
    }

    const float* pa = sA + mIdx * 8;
    const float* pb = sB + nIdx * 8;

#pragma unroll
    for (int kt = 0; kt < NT; kt++) {
        const int k0 = kt * KT;
        __syncthreads();
        load_A_tile<F, FIRST>(sA, xin, hin, sSrc, m0, k0, tid);
        for (int idx = tid; idx < KT * (TC / 4); idx += NTHR) {
            int kk = idx >> 5, q = idx & 31;
            *reinterpret_cast<float4*>(sB + kk * TC + q * 4) =
                *reinterpret_cast<const float4*>(Bc + (size_t)(k0 + kk) * G4 + c0 + q * 4);
        }
        __syncthreads();

#pragma unroll 4
        for (int kk = 0; kk < KT; kk++) {
            const float* ra = pa + kk * AST2;
            const float* rb = pb + kk * TC;
            ulonglong2 a01 = *reinterpret_cast<const ulonglong2*>(ra);
            ulonglong2 a23 = *reinterpret_cast<const ulonglong2*>(ra + 4);
            ulonglong2 b01 = *reinterpret_cast<const ulonglong2*>(rb);
            ulonglong2 b23 = *reinterpret_cast<const ulonglong2*>(rb + 4);
            u64 a[4] = {a01.x, a01.y, a23.x, a23.y};
            u64 b[4] = {b01.x, b01.y, b23.x, b23.y};
#pragma unroll
            for (int i = 0; i < 4; i++)
#pragma unroll
                for (int j = 0; j < 4; j++) fma2(acc[i][j], a[i], b[j]);
        }
    }

    // epilogue: cols interleaved (unit*4 + gate); this thread owns units u0,u0+1
    const int u0 = (c0 >> 2) + nIdx * 2;
#pragma unroll
    for (int i = 0; i < 4; i++) {
        int n = m0 + mIdx * 4 + i;
        if (n < N) {
            float2 p0 = *reinterpret_cast<float2*>(&acc[i][0]);  // i,f of u0
            float2 p1 = *reinterpret_cast<float2*>(&acc[i][1]);  // g,o of u0
            float2 p2 = *reinterpret_cast<float2*>(&acc[i][2]);  // i,f of u0+1
            float2 p3 = *reinterpret_cast<float2*>(&acc[i][3]);  // g,o of u0+1
            float gv[2][4] = {{p0.x, p0.y, p1.x, p1.y}, {p2.x, p2.y, p3.x, p3.y}};
#pragma unroll
            for (int uu = 0; uu < 2; uu++) {
                float gi = sigf(gv[uu][0]);
                float gf = sigf(gv[uu][1]);
                float gg = tanhfast(gv[uu][2]);
                float go = sigf(gv[uu][3]);
                int u = u0 + uu;
                float cold = FIRST ? 0.0f : cst[n * LH + u];
                float cn = gf * cold + gi * gg;
                cst[n * LH + u]  = cn;
                hout[n * LH + u] = go * tanhfast(cn);
            }
        }
    }
}

// ------------------------- linear + ReLU + LayerNorm ------------------------
template <int F, bool RELU_OUT>
__global__ void __launch_bounds__(NTHR, 3)
out_kernel(const float* __restrict__ xin, const float* __restrict__ hfin,
           const float* __restrict__ LT, const float* __restrict__ lb,
           const float* __restrict__ gma, const float* __restrict__ bta,
           float* __restrict__ out) {
    constexpr int K  = F + LH;
    constexpr int NT = K / KT;
    extern __shared__ float smem[];
    float* sA = smem;              // [KT][AST2]
    float* sB = smem + KT * AST2;  // [KT][HID]; later reused as sV [TM][VST]
    float* sV = sB;
    __shared__ float sMu[TM], sR[TM];

    const int tid = threadIdx.x;
    const int m0  = blockIdx.x * TM;
    const int nIdx = tid & 15;
    const int mIdx = tid >> 4;

    u64 acc[4][4];
    {
        const ulonglong2* bp = reinterpret_cast<const ulonglong2*>(lb + nIdx * 8);
        ulonglong2 b0 = bp[0], b1 = bp[1];
        u64 bj[4] = {b0.x, b0.y, b1.x, b1.y};
#pragma unroll
        for (int i = 0; i < 4; i++)
#pragma unroll
            for (int j = 0; j < 4; j++) acc[i][j] = bj[j];
    }

    const float* pa = sA + mIdx * 8;
    const float* pb = sB + nIdx * 8;

#pragma unroll
    for (int kt = 0; kt < NT; kt++) {
        const int k0 = kt * KT;
        __syncthreads();
        // A tile: x rows (k<F) or h rows (k>=F), duplicated layout, direct rows
        if (k0 < F) {
            for (int idx = tid; idx < TM * (KT / 4); idx += NTHR) {
                int m = idx >> 4, q = idx & 15;
                float4 v = make_float4(0.f, 0.f, 0.f, 0.f);
                if (m0 + m < N)
                    v = *reinterpret_cast<const float4*>(xin + (size_t)(m0 + m) * F + k0 + q * 4);
                float* d = sA + (q * 4) * AST2 + 2 * m;
                *reinterpret_cast<float2*>(d)            = make_float2(v.x, v.x);
                *reinterpret_cast<float2*>(d + AST2)     = make_float2(v.y, v.y);
                *reinterpret_cast<float2*>(d + 2 * AST2) = make_float2(v.z, v.z);
                *reinterpret_cast<float2*>(d + 3 * AST2) = make_float2(v.w, v.w);
            }
        } else {
            for (int idx = tid; idx < TM * (KT / 4); idx += NTHR) {
                int m = idx >> 4, q = idx & 15;
                float4 v = make_float4(0.f, 0.f, 0.f, 0.f);
                if (m0 + m < N)
                    v = *reinterpret_cast<const float4*>(hfin + (size_t)(m0 + m) * LH + (k0 - F) + q * 4);
                float* d = sA + (q * 4) * AST2 + 2 * m;
                *reinterpret_cast<float2*>(d)            = make_float2(v.x, v.x);
                *reinterpret_cast<float2*>(d + AST2)     = make_float2(v.y, v.y);
                *reinterpret_cast<float2*>(d + 2 * AST2) = make_float2(v.z, v.z);
                *reinterpret_cast<float2*>(d + 3 * AST2) = make_float2(v.w, v.w);
            }
        }
        for (int idx = tid; idx < KT * (HID / 4); idx += NTHR) {
            int kk = idx >> 5, q = idx & 31;
            *reinterpret_cast<float4*>(sB + kk * HID + q * 4) =
                *reinterpret_cast<const float4*>(LT + (size_t)(k0 + kk) * HID + q * 4);
        }
        __syncthreads();

#pragma unroll 4
        for (int kk = 0; kk < KT; kk++) {
            const float* ra = pa + kk * AST2;
            const float* rb = pb + kk * HID;
            ulonglong2 a01 = *reinterpret_cast<const ulonglong2*>(ra);
            ulonglong2 a23 = *reinterpret_cast<const ulonglong2*>(ra + 4);
            ulonglong2 b01 = *reinterpret_cast<const ulonglong2*>(rb);
            ulonglong2 b23 = *reinterpret_cast<const ulonglong2*>(rb + 4);
            u64 a[4] = {a01.x, a01.y, a23.x, a23.y};
            u64 b[4] = {b01.x, b01.y, b23.x, b23.y};
#pragma unroll
            for (int i = 0; i < 4; i++)
#pragma unroll
                for (int j = 0; j < 4; j++) fma2(acc[i][j], a[i], b[j]);
        }
    }
    __syncthreads();  // all sB reads done before overlaying sV

#pragma unroll
    for (int i = 0; i < 4; i++) {
        float* row = sV + (mIdx * 4 + i) * VST + nIdx * 8;
#pragma unroll
        for (int j = 0; j < 4; j++) {
            float2 p = *reinterpret_cast<float2*>(&acc[i][j]);
            row[2 * j + 0] = fmaxf(p.x, 0.0f);
            row[2 * j + 1] = fmaxf(p.y, 0.0f);
        }
    }
    __syncthreads();

    if (tid < TM) {
        float s = 0.0f, s2 = 0.0f;
        for (int cidx = 0; cidx < HID; cidx++) {
            float v = sV[tid * VST + cidx];
            s += v; s2 += v * v;
        }
        float mu  = s * (1.0f / HID);
        float var = s2 * (1.0f / HID) - mu * mu;
        sMu[tid] = mu;
        sR[tid]  = rsqrtf(var + EPS);
    }
    __syncthreads();

    for (int idx = tid; idx < TM * HID; idx += NTHR) {
        int m = idx / HID, cc = idx % HID;
        int n = m0 + m;
        if (n < N) {
            float v = (sV[m * VST + cc] - sMu[m]) * sR[m] * gma[cc] + bta[cc];
            out[n * HID + cc] = RELU_OUT ? fmaxf(v, 0.0f) : v;
        }
    }
}

// ------------------------- launch --------------------------------------------
extern "C" void kernel_launch(void* const* d_in, const int* in_sizes, int n_in,
                              void* d_out, int out_size) {
    const float* x    = (const float*)d_in[0];
    const int*   eraw = (const int*)d_in[1];
    const float* W1ih = (const float*)d_in[2];
    const float* W1hh = (const float*)d_in[3];
    const float* b1   = (const float*)d_in[4];
    const float* l1W  = (const float*)d_in[5];
    const float* l1b  = (const float*)d_in[6];
    const float* g1   = (const float*)d_in[7];
    const float* be1  = (const float*)d_in[8];
    const float* W2ih = (const float*)d_in[9];
    const float* W2hh = (const float*)d_in[10];
    const float* b2   = (const float*)d_in[11];
    const float* l2W  = (const float*)d_in[12];
    const float* l2b  = (const float*)d_in[13];
    const float* g2   = (const float*)d_in[14];
    const float* be2  = (const float*)d_in[15];

    float *pBc1, *pBc2, *pbc1, *pbc2, *pL1, *pL2, *phA, *phB, *pc, *ph1;
    cudaGetSymbolAddress((void**)&pBc1, g_Bc1);
    cudaGetSymbolAddress((void**)&pBc2, g_Bc2);
    cudaGetSymbolAddress((void**)&pbc1, g_bc1);
    cudaGetSymbolAddress((void**)&pbc2, g_bc2);
    cudaGetSymbolAddress((void**)&pL1, g_L1T);
    cudaGetSymbolAddress((void**)&pL2, g_L2T);
    cudaGetSymbolAddress((void**)&phA, g_hA);
    cudaGetSymbolAddress((void**)&phB, g_hB);
    cudaGetSymbolAddress((void**)&pc, g_cS);
    cudaGetSymbolAddress((void**)&ph1, g_h1);

    const int s_lstm = (KT * AST2 + KT * TC) * 4;   // 66,560 B
    const int s_out  = (KT * AST2 + TM * VST) * 4;  // 67,584 B (sV area >= sB area)

    cudaFuncSetAttribute((const void*)lstm_step_kernel<F1, true>,
                         cudaFuncAttributeMaxDynamicSharedMemorySize, s_lstm);
    cudaFuncSetAttribute((const void*)lstm_step_kernel<F1, false>,
                         cudaFuncAttributeMaxDynamicSharedMemorySize, s_lstm);
    cudaFuncSetAttribute((const void*)lstm_step_kernel<HID, true>,
                         cudaFuncAttributeMaxDynamicSharedMemorySize, s_lstm);
    cudaFuncSetAttribute((const void*)lstm_step_kernel<HID, false>,
                         cudaFuncAttributeMaxDynamicSharedMemorySize, s_lstm);
    cudaFuncSetAttribute((const void*)out_kernel<F1, true>,
                         cudaFuncAttributeMaxDynamicSharedMemorySize, s_out);
    cudaFuncSetAttribute((const void*)out_kernel<HID, false>,
                         cudaFuncAttributeMaxDynamicSharedMemorySize, s_out);

    cvt_src_kernel<<<(E + 1023) / 1024, 1024>>>(eraw);
    prep_kernel<<<256, 256>>>(W1ih, W1hh, b1, l1W, W2ih, W2hh, b2, l2W);

    const dim3 sgrid(MB, G4 / TC);  // 782 x 4

    // ---------------- layer 1 ----------------
    lstm_step_kernel<F1, true><<<sgrid, NTHR, s_lstm>>>(x, 0, pBc1, pbc1,
                                                        phB, phA, pc);
    for (int t = 1; t < DEG; t++) {
        float* hw = (t & 1) ? phB : phA;
        float* hr = (t & 1) ? phA : phB;
        lstm_step_kernel<F1, false><<<sgrid, NTHR, s_lstm>>>(x, t, pBc1, pbc1,
                                                             hr, hw, pc);
    }
    // DEG-1 = 7 odd -> final h in phB
    out_kernel<F1, true><<<MB, NTHR, s_out>>>(x, phB, pL1, l1b, g1, be1, ph1);

    // ---------------- layer 2 ----------------
    lstm_step_kernel<HID, true><<<sgrid, NTHR, s_lstm>>>(ph1, 0, pBc2, pbc2,
                                                         phB, phA, pc);
    for (int t = 1; t < DEG; t++) {
        float* hw = (t & 1) ? phB : phA;
        float* hr = (t & 1) ? phA : phB;
        lstm_step_kernel<HID, false><<<sgrid, NTHR, s_lstm>>>(ph1, t, pBc2, pbc2,
                                                              hr, hw, pc);
    }
    out_kernel<HID, false><<<MB, NTHR, s_out>>>(ph1, phB, pL2, l2b, g2, be2,
                                                (float*)d_out);
}

// round 3
// speedup vs baseline: 2.4329x; 1.7531x over previous
#include <cuda_runtime.h>

typedef unsigned long long u64;

// ---------------------------------------------------------------------------
// GraphSAGE (LSTM aggregation), 2 layers. N=50000, DEG=8, F_IN=64, HID=LH=128.
// R3: 8m x 8n register tile per thread (128 thr), conflict-free B reads,
//     transposed+padded recurrent state, KT=32 smem tiles, fma.rn.f32x2 core.
// ---------------------------------------------------------------------------

namespace cfg {
constexpr int N    = 50000;
constexpr int NP   = 50048;              // padded to TM multiple
constexpr int DEG  = 8;
constexpr int E    = N * DEG;
constexpr int F1   = 64;
constexpr int HID  = 128;
constexpr int LH   = 128;
constexpr int G4   = 4 * LH;             // 512 gate columns
constexpr int TM   = 64;                 // nodes per block
constexpr int TC   = 128;                // gate columns per block
constexpr int NTHR = 128;
constexpr int KT   = 32;                 // K tile
constexpr int AST2 = 2 * TM + 4;         // dup-A row stride (132 floats)
constexpr int VST  = HID + 4;            // 132
constexpr int MB   = (N + TM - 1) / TM;  // 782
constexpr float EPS = 1e-5f;
}
using namespace cfg;

// ------------------------- device scratch (no allocs) ----------------------
__device__ float g_Bc1[(F1 + LH) * G4];   // interleaved [K][512], col = u*4+gate
__device__ float g_Bc2[(HID + LH) * G4];
__device__ float g_bc1[G4];
__device__ float g_bc2[G4];
__device__ float g_L1T[(F1 + LH) * HID];  // lin W transposed [K][HID]
__device__ float g_L2T[(HID + LH) * HID];
__device__ float g_hA[LH * NP];           // h double buffer, TRANSPOSED [u][n]
__device__ float g_hB[LH * NP];
__device__ float g_cS[LH * NP];           // cell state, TRANSPOSED [u][n]
__device__ float g_h1[N * HID];           // layer-1 output (row-major, gathered)
__device__ int   g_src[E];                // normalized int32 source indices

// ------------------------- helpers -----------------------------------------
__device__ __forceinline__ float sigf(float x) {
    return __fdividef(1.0f, 1.0f + __expf(-x));
}
__device__ __forceinline__ float tanhfast(float x) {
    return __fdividef(2.0f, 1.0f + __expf(-2.0f * x)) - 1.0f;
}
__device__ __forceinline__ void fma2(u64& d, u64 a, u64 b) {
    asm("fma.rn.f32x2 %0, %1, %2, %0;" : "+l"(d) : "l"(a), "l"(b));
}
__device__ __forceinline__ float2 unpk(u64 v) {
    float2 r;
    asm("mov.b64 {%0, %1}, %2;" : "=f"(r.x), "=f"(r.y) : "l"(v));
    return r;
}

// Normalize edge_index src row to int32, robust to int64-vs-int32 dtype.
__global__ void cvt_src_kernel(const int* __restrict__ raw) {
    bool w64 = true;
#pragma unroll
    for (int i = 0; i < 32; i++) w64 &= (raw[2 * i + 1] == 0);
    for (int idx = blockIdx.x * blockDim.x + threadIdx.x; idx < E;
         idx += gridDim.x * blockDim.x)
        g_src[idx] = w64 ? raw[2 * idx] : raw[idx];
}

// Build interleaved/transposed weights once per call.
__global__ void prep_kernel(const float* __restrict__ W1ih, const float* __restrict__ W1hh,
                            const float* __restrict__ b1,   const float* __restrict__ l1W,
                            const float* __restrict__ W2ih, const float* __restrict__ W2hh,
                            const float* __restrict__ b2,   const float* __restrict__ l2W) {
    const int stride = gridDim.x * blockDim.x;
    const int t0 = blockIdx.x * blockDim.x + threadIdx.x;
    constexpr int K1 = F1 + LH, K2 = HID + LH;
    for (int idx = t0; idx < K1 * G4; idx += stride) {
        int k = idx / G4, cc = idx % G4, u = cc >> 2, g = cc & 3, row = g * LH + u;
        g_Bc1[idx] = (k < F1) ? W1ih[row * F1 + k] : W1hh[row * LH + (k - F1)];
    }
    for (int idx = t0; idx < K2 * G4; idx += stride) {
        int k = idx / G4, cc = idx % G4, u = cc >> 2, g = cc & 3, row = g * LH + u;
        g_Bc2[idx] = (k < HID) ? W2ih[row * HID + k] : W2hh[row * LH + (k - HID)];
    }
    for (int idx = t0; idx < G4; idx += stride) {
        int u = idx >> 2, g = idx & 3;
        g_bc1[idx] = b1[g * LH + u];
        g_bc2[idx] = b2[g * LH + u];
    }
    for (int idx = t0; idx < K1 * HID; idx += stride) {
        int k = idx / HID, cc = idx % HID;
        g_L1T[idx] = l1W[cc * K1 + k];
    }
    for (int idx = t0; idx < K2 * HID; idx += stride) {
        int k = idx / HID, cc = idx % HID;
        g_L2T[idx] = l2W[cc * K2 + k];
    }
}

// ------------------------- LSTM step ----------------------------------------
// gates[TM x TC] = [x[src_t] | h_in][TM x K] @ Bc_slice[K x TC] (+ bias)
// A-tile smem is value-duplicated along m: sA[kk][2m] = sA[kk][2m+1].
template <int F, bool FIRST>
__global__ void __launch_bounds__(NTHR, 3)
lstm_step_kernel(const float* __restrict__ xin, int t,
                 const float* __restrict__ Bc, const float* __restrict__ bc,
                 const float* __restrict__ hinT, float* __restrict__ houtT,
                 float* __restrict__ cstT) {
    constexpr int K  = FIRST ? F : (F + LH);
    constexpr int NT = K / KT;
    __shared__ float sA[KT][AST2];
    __shared__ float sB[KT][TC];
    __shared__ int sSrc[TM];

    const int tid  = threadIdx.x;
    const int m0   = blockIdx.x * TM;
    const int c0   = blockIdx.y * TC;
    const int nIdx = tid & 15;   // 16 col-groups
    const int mIdx = tid >> 4;   // 8 node-groups x 8 nodes

    if (tid < TM) {
        int n = m0 + tid;
        sSrc[tid] = (n < N) ? g_src[n * DEG + t] : 0;
    }

    u64 acc[8][4];
    {
        ulonglong2 b0 = *reinterpret_cast<const ulonglong2*>(bc + c0 + nIdx * 4);
        ulonglong2 b1 = *reinterpret_cast<const ulonglong2*>(bc + c0 + 64 + nIdx * 4);
        u64 bj[4] = {b0.x, b0.y, b1.x, b1.y};
#pragma unroll
        for (int i = 0; i < 8; i++)
#pragma unroll
            for (int j = 0; j < 4; j++) acc[i][j] = bj[j];
    }

#pragma unroll 1
    for (int kt = 0; kt < NT; kt++) {
        const int k0 = kt * KT;
        __syncthreads();
        if (FIRST || k0 < F) {
            // gather path: per idx one m, 4 k's (float4 row read), dup-store
#pragma unroll
            for (int it = 0; it < 4; it++) {
                int idx = tid + it * NTHR;          // 0..511
                int m = idx & 63, kq = idx >> 6;    // kq 0..7
                float4 v = *reinterpret_cast<const float4*>(
                    xin + (size_t)sSrc[m] * F + k0 + kq * 4);
                float* d0 = &sA[kq * 4 + 0][2 * m];
                float* d1 = &sA[kq * 4 + 1][2 * m];
                float* d2 = &sA[kq * 4 + 2][2 * m];
                float* d3 = &sA[kq * 4 + 3][2 * m];
                *reinterpret_cast<float2*>(d0) = make_float2(v.x, v.x);
                *reinterpret_cast<float2*>(d1) = make_float2(v.y, v.y);
                *reinterpret_cast<float2*>(d2) = make_float2(v.z, v.z);
                *reinterpret_cast<float2*>(d3) = make_float2(v.w, v.w);
            }
        } else {
            // transposed-h path: contiguous row copy, conflict-free dup-store
#pragma unroll
            for (int it = 0; it < 8; it++) {
                int idx = tid + it * NTHR;          // 0..1023
                int kk = idx >> 5, p = idx & 31;
                float2 v = *reinterpret_cast<const float2*>(
                    hinT + (size_t)(k0 - F + kk) * NP + m0 + 2 * p);
                *reinterpret_cast<float4*>(&sA[kk][4 * p]) =
                    make_float4(v.x, v.x, v.y, v.y);
            }
        }
#pragma unroll
        for (int it = 0; it < 8; it++) {
            int idx = tid + it * NTHR;
            int kk = idx >> 5, q = idx & 31;
            *reinterpret_cast<float4*>(&sB[kk][4 * q]) =
                *reinterpret_cast<const float4*>(Bc + (size_t)(k0 + kk) * G4 + c0 + 4 * q);
        }
        __syncthreads();

#pragma unroll 8
        for (int kk = 0; kk < KT; kk++) {
            const float* ra = &sA[kk][mIdx * 16];
            ulonglong2 a0 = *reinterpret_cast<const ulonglong2*>(ra);
            ulonglong2 a1 = *reinterpret_cast<const ulonglong2*>(ra + 4);
            ulonglong2 a2 = *reinterpret_cast<const ulonglong2*>(ra + 8);
            ulonglong2 a3 = *reinterpret_cast<const ulonglong2*>(ra + 12);
            ulonglong2 b01 = *reinterpret_cast<const ulonglong2*>(&sB[kk][nIdx * 4]);
            ulonglong2 b23 = *reinterpret_cast<const ulonglong2*>(&sB[kk][64 + nIdx * 4]);
            u64 a[8] = {a0.x, a0.y, a1.x, a1.y, a2.x, a2.y, a3.x, a3.y};
            u64 b[4] = {b01.x, b01.y, b23.x, b23.y};
#pragma unroll
            for (int i = 0; i < 8; i++)
#pragma unroll
                for (int j = 0; j < 4; j++) fma2(acc[i][j], a[i], b[j]);
        }
    }

    // epilogue: thread owns units u0 = c0/4 + nIdx and u0 + 16, 8 consecutive n
    const int u0 = (c0 >> 2) + nIdx;
    const int u1 = u0 + 16;
    const int nb = m0 + mIdx * 8;
    float h0[8], h1v[8], c0v[8], c1v[8];
    float co0[8], co1[8];
    if (!FIRST) {
#pragma unroll
        for (int q = 0; q < 2; q++) {
            float4 a = *reinterpret_cast<const float4*>(cstT + (size_t)u0 * NP + nb + 4 * q);
            float4 b = *reinterpret_cast<const float4*>(cstT + (size_t)u1 * NP + nb + 4 * q);
            co0[4 * q] = a.x; co0[4 * q + 1] = a.y; co0[4 * q + 2] = a.z; co0[4 * q + 3] = a.w;
            co1[4 * q] = b.x; co1[4 * q + 1] = b.y; co1[4 * q + 2] = b.z; co1[4 * q + 3] = b.w;
        }
    }
#pragma unroll
    for (int i = 0; i < 8; i++) {
        float2 if0 = unpk(acc[i][0]);   // (i, f) of u0
        float2 go0 = unpk(acc[i][1]);   // (g, o) of u0
        float2 if1 = unpk(acc[i][2]);
        float2 go1 = unpk(acc[i][3]);
        {
            float cn = sigf(if0.y) * (FIRST ? 0.0f : co0[i]) + sigf(if0.x) * tanhfast(go0.x);
            c0v[i] = cn;
            h0[i]  = sigf(go0.y) * tanhfast(cn);
        }
        {
            float cn = sigf(if1.y) * (FIRST ? 0.0f : co1[i]) + sigf(if1.x) * tanhfast(go1.x);
            c1v[i] = cn;
            h1v[i] = sigf(go1.y) * tanhfast(cn);
        }
    }
#pragma unroll
    for (int q = 0; q < 2; q++) {
        *reinterpret_cast<float4*>(cstT + (size_t)u0 * NP + nb + 4 * q) =
            make_float4(c0v[4 * q], c0v[4 * q + 1], c0v[4 * q + 2], c0v[4 * q + 3]);
        *reinterpret_cast<float4*>(cstT + (size_t)u1 * NP + nb + 4 * q) =
            make_float4(c1v[4 * q], c1v[4 * q + 1], c1v[4 * q + 2], c1v[4 * q + 3]);
        *reinterpret_cast<float4*>(houtT + (size_t)u0 * NP + nb + 4 * q) =
            make_float4(h0[4 * q], h0[4 * q + 1], h0[4 * q + 2], h0[4 * q + 3]);
        *reinterpret_cast<float4*>(houtT + (size_t)u1 * NP + nb + 4 * q) =
            make_float4(h1v[4 * q], h1v[4 * q + 1], h1v[4 * q + 2], h1v[4 * q + 3]);
    }
}

// ------------------------- linear + ReLU + LayerNorm ------------------------
template <int F, bool RELU_OUT>
__global__ void __launch_bounds__(NTHR, 3)
out_kernel(const float* __restrict__ xin, const float* __restrict__ hfinT,
           const float* __restrict__ LT, const float* __restrict__ lb,
           const float* __restrict__ gma, const float* __restrict__ bta,
           float* __restrict__ out) {
    constexpr int K  = F + LH;
    constexpr int NT = K / KT;
    __shared__ float pool[TM * VST];  // 8448 floats >= KT*AST2 + KT*HID (8320)
    float* sAf = pool;                           // [KT][AST2]
    float* sBf = pool + KT * AST2;               // [KT][HID]
    float* sV  = pool;                           // [TM][VST] (after compute)
    __shared__ float sMu[TM], sR[TM];

    const int tid  = threadIdx.x;
    const int m0   = blockIdx.x * TM;
    const int nIdx = tid & 15;
    const int mIdx = tid >> 4;

    u64 acc[8][4];
    {
        ulonglong2 b0 = *reinterpret_cast<const ulonglong2*>(lb + nIdx * 4);
        ulonglong2 b1 = *reinterpret_cast<const ulonglong2*>(lb + 64 + nIdx * 4);
        u64 bj[4] = {b0.x, b0.y, b1.x, b1.y};
#pragma unroll
        for (int i = 0; i < 8; i++)
#pragma unroll
            for (int j = 0; j < 4; j++) acc[i][j] = bj[j];
    }

#pragma unroll 1
    for (int kt = 0; kt < NT; kt++) {
        const int k0 = kt * KT;
        __syncthreads();
        if (k0 < F) {
#pragma unroll
            for (int it = 0; it < 4; it++) {
                int idx = tid + it * NTHR;
                int m = idx & 63, kq = idx >> 6;
                int row = m0 + m;
                row = row < N ? row : N - 1;
                float4 v = *reinterpret_cast<const float4*>(
                    xin + (size_t)row * F + k0 + kq * 4);
                float* base = sAf + (size_t)(kq * 4) * AST2 + 2 * m;
                *reinterpret_cast<float2*>(base)             = make_float2(v.x, v.x);
                *reinterpret_cast<float2*>(base + AST2)      = make_float2(v.y, v.y);
                *reinterpret_cast<float2*>(base + 2 * AST2)  = make_float2(v.z, v.z);
                *reinterpret_cast<float2*>(base + 3 * AST2)  = make_float2(v.w, v.w);
            }
        } else {
#pragma unroll
            for (int it = 0; it < 8; it++) {
                int idx = tid + it * NTHR;
                int kk = idx >> 5, p = idx & 31;
                float2 v = *reinterpret_cast<const float2*>(
                    hfinT + (size_t)(k0 - F + kk) * NP + m0 + 2 * p);
                *reinterpret_cast<float4*>(sAf + (size_t)kk * AST2 + 4 * p) =
                    make_float4(v.x, v.x, v.y, v.y);
            }
        }
#pragma unroll
        for (int it = 0; it < 8; it++) {
            int idx = tid + it * NTHR;
            int kk = idx >> 5, q = idx & 31;
            *reinterpret_cast<float4*>(sBf + (size_t)kk * HID + 4 * q) =
                *reinterpret_cast<const float4*>(LT + (size_t)(k0 + kk) * HID + 4 * q);
        }
        __syncthreads();

#pragma unroll 8
        for (int kk = 0; kk < KT; kk++) {
            const float* ra = sAf + (size_t)kk * AST2 + mIdx * 16;
            const float* rb = sBf + (size_t)kk * HID;
            ulonglong2 a0 = *reinterpret_cast<const ulonglong2*>(ra);
            ulonglong2 a1 = *reinterpret_cast<const ulonglong2*>(ra + 4);
            ulonglong2 a2 = *reinterpret_cast<const ulonglong2*>(ra + 8);
            ulonglong2 a3 = *reinterpret_cast<const ulonglong2*>(ra + 12);
            ulonglong2 b01 = *reinterpret_cast<const ulonglong2*>(rb + nIdx * 4);
            ulonglong2 b23 = *reinterpret_cast<const ulonglong2*>(rb + 64 + nIdx * 4);
            u64 a[8] = {a0.x, a0.y, a1.x, a1.y, a2.x, a2.y, a3.x, a3.y};
            u64 b[4] = {b01.x, b01.y, b23.x, b23.y};
#pragma unroll
            for (int i = 0; i < 8; i++)
#pragma unroll
                for (int j = 0; j < 4; j++) fma2(acc[i][j], a[i], b[j]);
        }
    }
    __syncthreads();  // finish all sA/sB reads before overlaying sV

#pragma unroll
    for (int i = 0; i < 8; i++) {
        float* row = sV + (size_t)(mIdx * 8 + i) * VST;
        float2 p0 = unpk(acc[i][0]), p1 = unpk(acc[i][1]);
        float2 p2 = unpk(acc[i][2]), p3 = unpk(acc[i][3]);
        *reinterpret_cast<float4*>(row + nIdx * 4) =
            make_float4(fmaxf(p0.x, 0.f), fmaxf(p0.y, 0.f), fmaxf(p1.x, 0.f), fmaxf(p1.y, 0.f));
        *reinterpret_cast<float4*>(row + 64 + nIdx * 4) =
            make_float4(fmaxf(p2.x, 0.f), fmaxf(p2.y, 0.f), fmaxf(p3.x, 0.f), fmaxf(p3.y, 0.f));
    }
    __syncthreads();

    if (tid < TM) {
        float s = 0.0f, s2 = 0.0f;
        for (int cidx = 0; cidx < HID; cidx++) {
            float v = sV[(size_t)tid * VST + cidx];
            s += v; s2 += v * v;
        }
        float mu  = s * (1.0f / HID);
        float var = s2 * (1.0f / HID) - mu * mu;
        sMu[tid] = mu;
        sR[tid]  = rsqrtf(var + EPS);
    }
    __syncthreads();

    for (int idx = tid; idx < TM * HID; idx += NTHR) {
        int m = idx >> 7, cc = idx & 127;
        int n = m0 + m;
        if (n < N) {
            float v = (sV[(size_t)m * VST + cc] - sMu[m]) * sR[m] * gma[cc] + bta[cc];
            out[(size_t)n * HID + cc] = RELU_OUT ? fmaxf(v, 0.0f) : v;
        }
    }
}

// ------------------------- launch --------------------------------------------
extern "C" void kernel_launch(void* const* d_in, const int* in_sizes, int n_in,
                              void* d_out, int out_size) {
    const float* x    = (const float*)d_in[0];
    const int*   eraw = (const int*)d_in[1];
    const float* W1ih = (const float*)d_in[2];
    const float* W1hh = (const float*)d_in[3];
    const float* b1   = (const float*)d_in[4];
    const float* l1W  = (const float*)d_in[5];
    const float* l1b  = (const float*)d_in[6];
    const float* g1   = (const float*)d_in[7];
    const float* be1  = (const float*)d_in[8];
    const float* W2ih = (const float*)d_in[9];
    const float* W2hh = (const float*)d_in[10];
    const float* b2   = (const float*)d_in[11];
    const float* l2W  = (const float*)d_in[12];
    const float* l2b  = (const float*)d_in[13];
    const float* g2   = (const float*)d_in[14];
    const float* be2  = (const float*)d_in[15];

    float *pBc1, *pBc2, *pbc1, *pbc2, *pL1, *pL2, *phA, *phB, *pc, *ph1;
    cudaGetSymbolAddress((void**)&pBc1, g_Bc1);
    cudaGetSymbolAddress((void**)&pBc2, g_Bc2);
    cudaGetSymbolAddress((void**)&pbc1, g_bc1);
    cudaGetSymbolAddress((void**)&pbc2, g_bc2);
    cudaGetSymbolAddress((void**)&pL1, g_L1T);
    cudaGetSymbolAddress((void**)&pL2, g_L2T);
    cudaGetSymbolAddress((void**)&phA, g_hA);
    cudaGetSymbolAddress((void**)&phB, g_hB);
    cudaGetSymbolAddress((void**)&pc, g_cS);
    cudaGetSymbolAddress((void**)&ph1, g_h1);

    cvt_src_kernel<<<(E + 1023) / 1024, 1024>>>(eraw);
    prep_kernel<<<256, 256>>>(W1ih, W1hh, b1, l1W, W2ih, W2hh, b2, l2W);

    const dim3 sgrid(MB, G4 / TC);  // 782 x 4

    // ---------------- layer 1 ----------------
    lstm_step_kernel<F1, true><<<sgrid, NTHR>>>(x, 0, pBc1, pbc1, phB, phA, pc);
    for (int t = 1; t < DEG; t++) {
        float* hw = (t & 1) ? phB : phA;
        float* hr = (t & 1) ? phA : phB;
        lstm_step_kernel<F1, false><<<sgrid, NTHR>>>(x, t, pBc1, pbc1, hr, hw, pc);
    }
    // DEG-1 = 7 odd -> final h in phB
    out_kernel<F1, true><<<MB, NTHR>>>(x, phB, pL1, l1b, g1, be1, ph1);

    // ---------------- layer 2 ----------------
    lstm_step_kernel<HID, true><<<sgrid, NTHR>>>(ph1, 0, pBc2, pbc2, phB, phA, pc);
    for (int t = 1; t < DEG; t++) {
        float* hw = (t & 1) ? phB : phA;
        float* hr = (t & 1) ? phA : phB;
        lstm_step_kernel<HID, false><<<sgrid, NTHR>>>(ph1, t, pBc2, pbc2, hr, hw, pc);
    }
    out_kernel<HID, false><<<MB, NTHR>>>(ph1, phB, pL2, l2b, g2, be2, (float*)d_out);
}